// round 4
// baseline (speedup 1.0000x reference)
#include <cuda_runtime.h>

// AdditiveEmission: local-window (w=3) additive attention.
//   q = X@Wt, k = X@Wx
//   e[i,j] = Wa . tanh(q_i + k_j + bh) + ba,  j in {i-1, i, i+1} (clipped)
//   a = softmax_window(e) with +EPS in denominator
//   out_i = sum_j a[i,j] * x_j
//
// B=4, L=512, D=128. One block = (batch b, tile of T=16 queries).
// Block computes its own q rows (T) and k rows (T+2) from SMEM-resident x rows,
// then does the windowed softmax + AV. Single launch, no scratch globals.

#define B_ 4
#define L_ 512
#define D_ 128
#define T_ 16
#define R_ (T_ + 2)
#define EPS_ 1e-8f

__global__ __launch_bounds__(D_, 1)
void additive_local_attn(const float* __restrict__ x,
                         const float* __restrict__ Wt,
                         const float* __restrict__ Wx,
                         const float* __restrict__ Wa,
                         const float* __restrict__ bh,
                         const float* __restrict__ ba,
                         float* __restrict__ out)
{
    __shared__ float xs[R_][D_];          // rows i0-1 .. i0+T of x (zero-padded at seq ends)
    __shared__ float sred[T_][4][3];      // per-t, per-warp partial sums of the 3 logits

    const int d    = threadIdx.x;
    const int lane = d & 31;
    const int warp = d >> 5;
    const int b    = blockIdx.y;
    const int i0   = blockIdx.x * T_;

    const float* xb = x + (size_t)b * L_ * D_;

    // ---- stage x rows [i0-1, i0+T] into SMEM ----
    #pragma unroll
    for (int r = 0; r < R_; ++r) {
        int g = i0 - 1 + r;
        xs[r][d] = (g >= 0 && g < L_) ? xb[g * D_ + d] : 0.0f;
    }
    __syncthreads();

    // ---- fused GEMV: q[t][d] = sum_e x[i0+t][e]*Wt[e][d]; k[r][d] likewise with Wx ----
    float qa[T_];
    float ka[R_];
    #pragma unroll
    for (int t = 0; t < T_; ++t) qa[t] = 0.0f;
    #pragma unroll
    for (int r = 0; r < R_; ++r) ka[r] = 0.0f;

    #pragma unroll 4
    for (int e = 0; e < D_; e += 4) {
        const float wt0 = Wt[(e + 0) * D_ + d];
        const float wt1 = Wt[(e + 1) * D_ + d];
        const float wt2 = Wt[(e + 2) * D_ + d];
        const float wt3 = Wt[(e + 3) * D_ + d];
        const float wx0 = Wx[(e + 0) * D_ + d];
        const float wx1 = Wx[(e + 1) * D_ + d];
        const float wx2 = Wx[(e + 2) * D_ + d];
        const float wx3 = Wx[(e + 3) * D_ + d];
        #pragma unroll
        for (int r = 0; r < R_; ++r) {
            const float4 xv = *reinterpret_cast<const float4*>(&xs[r][e]);
            // row r feeds k[r] ...
            float kacc = ka[r];
            kacc = fmaf(xv.x, wx0, kacc);
            kacc = fmaf(xv.y, wx1, kacc);
            kacc = fmaf(xv.z, wx2, kacc);
            kacc = fmaf(xv.w, wx3, kacc);
            ka[r] = kacc;
            // ... and q[r-1] (row r is global query i0+r-1)
            if (r >= 1 && r <= T_) {
                float qacc = qa[r - 1];
                qacc = fmaf(xv.x, wt0, qacc);
                qacc = fmaf(xv.y, wt1, qacc);
                qacc = fmaf(xv.z, wt2, qacc);
                qacc = fmaf(xv.w, wt3, qacc);
                qa[r - 1] = qacc;
            }
        }
    }

    // ---- logits: e_j(t) = sum_d Wa[d]*tanh(q[t][d] + k[t+j][d] + bh[d]) ----
    const float wad = Wa[d];
    const float bhd = bh[d];

    #pragma unroll
    for (int t = 0; t < T_; ++t) {
        float p0 = wad * tanhf(qa[t] + ka[t]     + bhd);
        float p1 = wad * tanhf(qa[t] + ka[t + 1] + bhd);
        float p2 = wad * tanhf(qa[t] + ka[t + 2] + bhd);
        #pragma unroll
        for (int off = 16; off; off >>= 1) {
            p0 += __shfl_xor_sync(0xffffffffu, p0, off);
            p1 += __shfl_xor_sync(0xffffffffu, p1, off);
            p2 += __shfl_xor_sync(0xffffffffu, p2, off);
        }
        if (lane == 0) {
            sred[t][warp][0] = p0;
            sred[t][warp][1] = p1;
            sred[t][warp][2] = p2;
        }
    }
    __syncthreads();

    // ---- windowed softmax (+EPS) and AV ----
    const float ba0 = ba[0];
    float* ob = out + (((size_t)b * L_ + i0) * D_ + d);

    #pragma unroll
    for (int t = 0; t < T_; ++t) {
        const int i = i0 + t;
        float e0 = sred[t][0][0] + sred[t][1][0] + sred[t][2][0] + sred[t][3][0] + ba0;
        float e1 = sred[t][0][1] + sred[t][1][1] + sred[t][2][1] + sred[t][3][1] + ba0;
        float e2 = sred[t][0][2] + sred[t][1][2] + sred[t][2][2] + sred[t][3][2] + ba0;

        const bool v0 = (i - 1) >= 0;
        const bool v2 = (i + 1) < L_;

        float m = e1;
        if (v0) m = fmaxf(m, e0);
        if (v2) m = fmaxf(m, e2);

        const float w0 = v0 ? expf(e0 - m) : 0.0f;
        const float w1 = expf(e1 - m);
        const float w2 = v2 ? expf(e2 - m) : 0.0f;

        const float inv = 1.0f / (w0 + w1 + w2 + EPS_);
        const float o = (w0 * xs[t][d] + w1 * xs[t + 1][d] + w2 * xs[t + 2][d]) * inv;
        ob[(size_t)t * D_] = o;
    }
}

extern "C" void kernel_launch(void* const* d_in, const int* in_sizes, int n_in,
                              void* d_out, int out_size)
{
    const float* x  = (const float*)d_in[0];
    const float* Wt = (const float*)d_in[1];
    const float* Wx = (const float*)d_in[2];
    const float* Wa = (const float*)d_in[3];
    const float* bh = (const float*)d_in[4];
    const float* ba = (const float*)d_in[5];
    float* out = (float*)d_out;

    dim3 grid(L_ / T_, B_);   // 32 x 4 = 128 blocks
    additive_local_attn<<<grid, D_>>>(x, Wt, Wx, Wa, bh, ba, out);
}

// round 5
// speedup vs baseline: 1.1382x; 1.1382x over previous
#include <cuda_runtime.h>

// AdditiveEmission: local-window (w=3) additive attention.
//   q = X@Wt, k = X@Wx
//   e[i,j] = Wa . tanh(q_i + k_j + bh) + ba,  j in {i-1, i, i+1} (clipped)
//   a = softmax_window(e) with +EPS in denominator
//   out_i = sum_j a[i,j] * x_j
//
// B=4, L=512, D=128. One block = (batch b, tile of T=8 queries) -> 256 blocks,
// ~2 blocks/SM on the 148-SM GB300 so each SMSP has 2 eligible warps.
// Block computes its own q rows (T) and k rows (T+2) from SMEM-resident x rows,
// then does the windowed softmax + AV. Single launch, no scratch globals.

#define B_ 4
#define L_ 512
#define D_ 128
#define T_ 8
#define R_ (T_ + 2)
#define EPS_ 1e-8f

__device__ __forceinline__ float tanh_approx(float v) {
    float r;
    asm("tanh.approx.f32 %0, %1;" : "=f"(r) : "f"(v));
    return r;
}

__global__ __launch_bounds__(D_)
void additive_local_attn(const float* __restrict__ x,
                         const float* __restrict__ Wt,
                         const float* __restrict__ Wx,
                         const float* __restrict__ Wa,
                         const float* __restrict__ bh,
                         const float* __restrict__ ba,
                         float* __restrict__ out)
{
    __shared__ float xs[R_][D_];          // rows i0-1 .. i0+T of x (zero-padded at seq ends)
    __shared__ float sred[T_][4][3];      // per-t, per-warp partial sums of the 3 logits

    const int d    = threadIdx.x;
    const int lane = d & 31;
    const int warp = d >> 5;
    const int b    = blockIdx.y;
    const int i0   = blockIdx.x * T_;

    const float* xb = x + (size_t)b * L_ * D_;

    // ---- stage x rows [i0-1, i0+T] into SMEM ----
    #pragma unroll
    for (int r = 0; r < R_; ++r) {
        int g = i0 - 1 + r;
        xs[r][d] = (g >= 0 && g < L_) ? xb[g * D_ + d] : 0.0f;
    }
    __syncthreads();

    // ---- fused GEMV: q[t][d] = sum_e x[i0+t][e]*Wt[e][d]; k[r][d] likewise with Wx ----
    float qa[T_];
    float ka[R_];
    #pragma unroll
    for (int t = 0; t < T_; ++t) qa[t] = 0.0f;
    #pragma unroll
    for (int r = 0; r < R_; ++r) ka[r] = 0.0f;

    #pragma unroll 4
    for (int e = 0; e < D_; e += 4) {
        const float wt0 = Wt[(e + 0) * D_ + d];
        const float wt1 = Wt[(e + 1) * D_ + d];
        const float wt2 = Wt[(e + 2) * D_ + d];
        const float wt3 = Wt[(e + 3) * D_ + d];
        const float wx0 = Wx[(e + 0) * D_ + d];
        const float wx1 = Wx[(e + 1) * D_ + d];
        const float wx2 = Wx[(e + 2) * D_ + d];
        const float wx3 = Wx[(e + 3) * D_ + d];
        #pragma unroll
        for (int r = 0; r < R_; ++r) {
            const float4 xv = *reinterpret_cast<const float4*>(&xs[r][e]);
            // row r feeds k[r] ...
            float kacc = ka[r];
            kacc = fmaf(xv.x, wx0, kacc);
            kacc = fmaf(xv.y, wx1, kacc);
            kacc = fmaf(xv.z, wx2, kacc);
            kacc = fmaf(xv.w, wx3, kacc);
            ka[r] = kacc;
            // ... and q[r-1] (row r is global query i0+r-1)
            if (r >= 1 && r <= T_) {
                float qacc = qa[r - 1];
                qacc = fmaf(xv.x, wt0, qacc);
                qacc = fmaf(xv.y, wt1, qacc);
                qacc = fmaf(xv.z, wt2, qacc);
                qacc = fmaf(xv.w, wt3, qacc);
                qa[r - 1] = qacc;
            }
        }
    }

    // ---- logits: e_j(t) = sum_d Wa[d]*tanh(q[t][d] + k[t+j][d] + bh[d]) ----
    const float wad = Wa[d];
    const float bhd = bh[d];

    #pragma unroll
    for (int t = 0; t < T_; ++t) {
        float p0 = wad * tanh_approx(qa[t] + ka[t]     + bhd);
        float p1 = wad * tanh_approx(qa[t] + ka[t + 1] + bhd);
        float p2 = wad * tanh_approx(qa[t] + ka[t + 2] + bhd);
        #pragma unroll
        for (int off = 16; off; off >>= 1) {
            p0 += __shfl_xor_sync(0xffffffffu, p0, off);
            p1 += __shfl_xor_sync(0xffffffffu, p1, off);
            p2 += __shfl_xor_sync(0xffffffffu, p2, off);
        }
        if (lane == 0) {
            sred[t][warp][0] = p0;
            sred[t][warp][1] = p1;
            sred[t][warp][2] = p2;
        }
    }
    __syncthreads();

    // ---- windowed softmax (+EPS) and AV ----
    const float ba0 = ba[0];
    float* ob = out + (((size_t)b * L_ + i0) * D_ + d);

    #pragma unroll
    for (int t = 0; t < T_; ++t) {
        const int i = i0 + t;
        float e0 = sred[t][0][0] + sred[t][1][0] + sred[t][2][0] + sred[t][3][0] + ba0;
        float e1 = sred[t][0][1] + sred[t][1][1] + sred[t][2][1] + sred[t][3][1] + ba0;
        float e2 = sred[t][0][2] + sred[t][1][2] + sred[t][2][2] + sred[t][3][2] + ba0;

        const bool v0 = (i - 1) >= 0;
        const bool v2 = (i + 1) < L_;

        float m = e1;
        if (v0) m = fmaxf(m, e0);
        if (v2) m = fmaxf(m, e2);

        const float w0 = v0 ? __expf(e0 - m) : 0.0f;
        const float w1 = __expf(e1 - m);
        const float w2 = v2 ? __expf(e2 - m) : 0.0f;

        const float inv = 1.0f / (w0 + w1 + w2 + EPS_);
        const float o = (w0 * xs[t][d] + w1 * xs[t + 1][d] + w2 * xs[t + 2][d]) * inv;
        ob[(size_t)t * D_] = o;
    }
}

extern "C" void kernel_launch(void* const* d_in, const int* in_sizes, int n_in,
                              void* d_out, int out_size)
{
    const float* x  = (const float*)d_in[0];
    const float* Wt = (const float*)d_in[1];
    const float* Wx = (const float*)d_in[2];
    const float* Wa = (const float*)d_in[3];
    const float* bh = (const float*)d_in[4];
    const float* ba = (const float*)d_in[5];
    float* out = (float*)d_out;

    dim3 grid(L_ / T_, B_);   // 64 x 4 = 256 blocks
    additive_local_attn<<<grid, D_>>>(x, Wt, Wx, Wa, bh, ba, out);
}